// round 11
// baseline (speedup 1.0000x reference)
#include <cuda_runtime.h>
#include <cuda_fp16.h>

#define BATCH 8
#define NPX   (512*512)          // 262144 pixels per sample
#define BPS   32                 // K1 blocks per sample -> 256 blocks
#define TPB1  512
#define NB    17408              // full fp16-code histogram (max code 0x4200=16896 < NB)
#define NW    (NB/2)             // packed u32 words per histogram
#define CPT   34                 // K2 codes per thread: NB / 512
#define EPS   1e-6f
#define SCALE_D 1099511627776.0  // 2^40 fixed-point scale

// ---------------- device scratch (zero-init at load; self-cleaning each run) ----
__device__ unsigned  g_hist[2][BATCH][NB];       // exact per-code counts (u32)
__device__ unsigned  g_count[BATCH];             // # unknown pixels per sample
__device__ unsigned long long g_loss[2][BATCH];  // fixed-point top-k sums
__device__ unsigned  g_done;                     // K2 completion counter

// ---------------- K1: fused value compute + count + full fp16 histogram ----
__global__ __launch_bounds__(TPB1) void k_compute(
    const float* __restrict__ image, const float* __restrict__ alpha,
    const float* __restrict__ pred,  const int*   __restrict__ trimap,
    const float* __restrict__ fg,    const float* __restrict__ bg)
{
    extern __shared__ unsigned sh[];             // [0..NW): A hist, [NW..2NW): C hist
    __shared__ unsigned shCnt;
    for (int i = threadIdx.x; i < 2 * NW; i += TPB1) sh[i] = 0u;
    if (threadIdx.x == 0) shCnt = 0u;
    __syncthreads();

    const int b     = blockIdx.x >> 5;           // / BPS
    const int chunk = blockIdx.x & (BPS - 1);
    const int base  = chunk * (NPX / BPS);       // 8192-pixel chunk
    const int CH4   = NPX / 4;                   // channel stride in float4

    const float4* al4 = (const float4*)(alpha  + (size_t)b * NPX + base);
    const float4* pr4 = (const float4*)(pred   + (size_t)b * NPX + base);
    const int4*   tm4 = (const int4*)  (trimap + (size_t)b * NPX + base);
    const float4* im4 = (const float4*)(image  + (size_t)b * 3 * NPX + base);
    const float4* fg4 = (const float4*)(fg     + (size_t)b * 3 * NPX + base);
    const float4* bg4 = (const float4*)(bg     + (size_t)b * 3 * NPX + base);

    unsigned cnt = 0;
    #pragma unroll
    for (int it = 0; it < (NPX / BPS) / 4 / TPB1; it++) {   // 4 iterations
        const int i = it * TPB1 + threadIdx.x;
        const int4   t = __ldcs(tm4 + i);
        const float4 a = __ldcs(al4 + i);
        const float4 p = __ldcs(pr4 + i);

        float da[4], dc[4];
        #pragma unroll
        for (int j = 0; j < 4; j++) {
            da[j] = fmaxf(fabsf(fmaf(((const float*)&a)[j], 1.0f/255.0f,
                                     -((const float*)&p)[j])), EPS);
            dc[j] = 0.0f;
        }
        #pragma unroll
        for (int ch = 0; ch < 3; ch++) {         // channel-incremental
            const float4 im = __ldcs(im4 + i + ch * CH4);
            const float4 ff = __ldcs(fg4 + i + ch * CH4);
            const float4 gg = __ldcs(bg4 + i + ch * CH4);
            #pragma unroll
            for (int j = 0; j < 4; j++) {
                float pj = ((const float*)&p)[j];
                float tt = fmaf(((const float*)&ff)[j] - ((const float*)&gg)[j], pj,
                                ((const float*)&gg)[j]);
                dc[j] += fmaxf(fabsf(((const float*)&im)[j] - tt), EPS);
            }
        }
        #pragma unroll
        for (int j = 0; j < 4; j++) {
            if (((const int*)&t)[j] == 128) {
                unsigned ca = (unsigned)__half_as_ushort(__float2half_rn(da[j]));
                unsigned cc = (unsigned)__half_as_ushort(__float2half_rn(dc[j]));
                ca = min(ca, (unsigned)(NB - 1));          // provable no-op; memory safety
                cc = min(cc, (unsigned)(NB - 1));
                atomicAdd(&sh[ca >> 1],      1u << ((ca & 1u) << 4));
                atomicAdd(&sh[NW + (cc >> 1)], 1u << ((cc & 1u) << 4));
                cnt++;
            }
        }
    }
    cnt = __reduce_add_sync(0xFFFFFFFFu, cnt);
    if ((threadIdx.x & 31) == 0 && cnt) atomicAdd(&shCnt, cnt);
    __syncthreads();
    if (threadIdx.x == 0 && shCnt) atomicAdd(&g_count[b], shCnt);

    // flush nonzero packed words to the global exact histogram
    for (int i = threadIdx.x; i < 2 * NW; i += TPB1) {
        unsigned wv = sh[i];
        if (wv) {
            const int arr = (i >= NW);
            const int wi  = arr ? (i - NW) : i;
            unsigned* gh = g_hist[arr][b];
            unsigned lo = wv & 0xFFFFu, hi = wv >> 16;
            if (lo) atomicAdd(&gh[2 * wi],     lo);
            if (hi) atomicAdd(&gh[2 * wi + 1], hi);
        }
    }
}

// ---------------- K2: exact descending scan + top-k sum + fused finish ----
__global__ __launch_bounds__(512) void k_select(float* __restrict__ out) {
    __shared__ unsigned s_wsum[16];
    __shared__ unsigned s_cut, s_krem;
    __shared__ unsigned long long s_sum;
    __shared__ bool s_last;

    const int arr = blockIdx.x >> 3;
    const int b   = blockIdx.x & 7;
    const int t   = threadIdx.x;
    const int lane = t & 31, w = t >> 5;
    unsigned* hist = g_hist[arr][b];

    if (t == 0) { s_cut = 0xFFFFFFFFu; s_krem = 0u; s_sum = 0ull; }

    // thread t owns codes base..base-33 (descending); t ascending = value descending
    const int base = NB - 1 - CPT * t;
    unsigned cnts[CPT];
    unsigned seg = 0;
    #pragma unroll
    for (int j = 0; j < CPT; j++) { cnts[j] = hist[base - j]; seg += cnts[j]; }
    #pragma unroll
    for (int j = 0; j < CPT; j++) hist[base - j] = 0u;    // self-clean for next replay

    // block-wide inclusive scan over seg (descending value order)
    unsigned incl = seg;
    #pragma unroll
    for (int d = 1; d < 32; d <<= 1) {
        unsigned v = __shfl_up_sync(0xFFFFFFFFu, incl, d);
        if (lane >= d) incl += v;
    }
    if (lane == 31) s_wsum[w] = incl;
    __syncthreads();
    if (t == 0) {
        unsigned run = 0;
        #pragma unroll
        for (int i = 0; i < 16; i++) { unsigned v = s_wsum[i]; s_wsum[i] = run; run += v; }
    }
    __syncthreads();
    incl += s_wsum[w];

    const unsigned k = (unsigned)(int)floorf((float)g_count[b] * 0.7f);
    {
        unsigned excl = incl - seg;
        if (k > 0u && excl < k && incl >= k) {             // exactly one owner thread
            unsigned cum = excl;
            #pragma unroll
            for (int j = 0; j < CPT; j++) {
                cum += cnts[j];
                if (cum >= k) {
                    s_cut  = (unsigned)(base - j);
                    s_krem = k - (cum - cnts[j]);          // >= 1
                    break;
                }
            }
        }
    }
    __syncthreads();
    const unsigned cut = s_cut;

    // order-independent fixed-point sum of count*value for codes above cut
    unsigned long long part = 0ull;
    #pragma unroll
    for (int j = 0; j < CPT; j++) {
        unsigned code = (unsigned)(base - j);
        if (code > cut && cnts[j]) {
            float v = __half2float(__ushort_as_half((unsigned short)code));
            part += (unsigned long long)((double)cnts[j] * (double)v * SCALE_D);
        }
    }
    if (t == 0 && cut != 0xFFFFFFFFu) {                    // tie-exact cut-bin take
        float v = __half2float(__ushort_as_half((unsigned short)cut));
        part += (unsigned long long)((double)s_krem * (double)v * SCALE_D);
    }
    if (part) atomicAdd(&s_sum, part);
    __syncthreads();
    if (t == 0) {
        g_loss[arr][b] = s_sum;
        __threadfence();
        s_last = (atomicAdd(&g_done, 1u) == 15u);
    }
    __syncthreads();
    if (!s_last) return;

    if (t == 0) {                                          // final combine (16 values)
        __threadfence();
        double sA = 0.0, sC = 0.0;
        for (int i = 0; i < BATCH; i++) {
            double kk = floor((double)(float)g_count[i] * 0.7);
            // recompute k per sample exactly as above (f32 floor path)
            float kf = floorf((float)g_count[i] * 0.7f);
            double la = ((double)g_loss[0][i] / SCALE_D) / ((double)kf + 1e-6);
            double lc = ((double)g_loss[1][i] / SCALE_D) / ((double)kf + 1e-6);
            if (kf <= 0.0f) { la = 0.0; lc = 0.0; }
            (void)kk;
            sA += la; sC += lc;
        }
        out[0] = 0.5f * (float)(sA / (double)BATCH) + 0.5f * (float)(sC / (double)BATCH);
        g_done = 0u;
        for (int i = 0; i < BATCH; i++) g_count[i] = 0u;   // self-clean
    }
}

// ---------------- launch ----------------
extern "C" void kernel_launch(void* const* d_in, const int* in_sizes, int n_in,
                              void* d_out, int out_size)
{
    const float* image  = (const float*)d_in[0];
    const float* alpha  = (const float*)d_in[1];
    const float* pred   = (const float*)d_in[2];
    const int*   trimap = (const int*)  d_in[3];
    const float* fg     = (const float*)d_in[4];
    const float* bg     = (const float*)d_in[5];

    static bool attr_set = false;
    if (!attr_set) {
        cudaFuncSetAttribute(k_compute, cudaFuncAttributeMaxDynamicSharedMemorySize,
                             2 * NW * (int)sizeof(unsigned));
        attr_set = true;
    }

    k_compute<<<BATCH * BPS, TPB1, 2 * NW * sizeof(unsigned)>>>(
        image, alpha, pred, trimap, fg, bg);
    k_select<<<16, 512>>>((float*)d_out);
}

// round 12
// speedup vs baseline: 1.7678x; 1.7678x over previous
#include <cuda_runtime.h>
#include <cuda_fp16.h>

#define BATCH 8
#define NPX   (512*512)          // 262144 pixels per sample
#define BPS   32                 // K1 blocks per sample -> 256 blocks
#define TPB1  512
#define NB    17408              // full fp16-code histogram (max code 0x4200=16896 < NB)
#define NW    (NB/2)             // packed u32 words per smem histogram
#define TPB2  544                // K2 threads: NB / 32 codes per thread
#define EPS   1e-6f
#define SCALE_D 1099511627776.0  // 2^40 (final normalize only)

// ---------------- device scratch (zero-init at load; self-cleaning each run) ----
__device__ unsigned  g_hist[2][BATCH][NB];       // exact per-code counts (u32)
__device__ unsigned  g_count[BATCH];             // # unknown pixels per sample
__device__ unsigned long long g_loss[2][BATCH];  // fixed-point top-k sums
__device__ unsigned  g_done;                     // K2 completion counter

// exact u64 fixed-point (x 2^40) decode of a half bit pattern (positive, < 2^15)
__device__ __forceinline__ unsigned long long h2fx(unsigned code) {
    unsigned e = code >> 10, m = code & 1023u;
    return e ? ((unsigned long long)(1024u + m) << (e + 15))
             : ((unsigned long long)m << 16);
}

// ---------------- K1: fused value compute + count + full fp16 histogram ----
__global__ __launch_bounds__(TPB1) void k_compute(
    const float* __restrict__ image, const float* __restrict__ alpha,
    const float* __restrict__ pred,  const int*   __restrict__ trimap,
    const float* __restrict__ fg,    const float* __restrict__ bg)
{
    extern __shared__ unsigned sh[];             // [0..NW): A hist, [NW..2NW): C hist
    __shared__ unsigned shCnt;
    for (int i = threadIdx.x; i < 2 * NW; i += TPB1) sh[i] = 0u;
    if (threadIdx.x == 0) shCnt = 0u;
    __syncthreads();

    const int b     = blockIdx.x >> 5;           // / BPS
    const int chunk = blockIdx.x & (BPS - 1);
    const int base  = chunk * (NPX / BPS);       // 8192-pixel chunk
    const int CH4   = NPX / 4;                   // channel stride in float4

    const float4* al4 = (const float4*)(alpha  + (size_t)b * NPX + base);
    const float4* pr4 = (const float4*)(pred   + (size_t)b * NPX + base);
    const int4*   tm4 = (const int4*)  (trimap + (size_t)b * NPX + base);
    const float4* im4 = (const float4*)(image  + (size_t)b * 3 * NPX + base);
    const float4* fg4 = (const float4*)(fg     + (size_t)b * 3 * NPX + base);
    const float4* bg4 = (const float4*)(bg     + (size_t)b * 3 * NPX + base);

    unsigned cnt = 0;
    #pragma unroll
    for (int it = 0; it < (NPX / BPS) / 4 / TPB1; it++) {   // 4 iterations
        const int i = it * TPB1 + threadIdx.x;
        const int4   t = __ldcs(tm4 + i);
        const float4 a = __ldcs(al4 + i);
        const float4 p = __ldcs(pr4 + i);

        float da[4], dc[4];
        #pragma unroll
        for (int j = 0; j < 4; j++) {
            da[j] = fmaxf(fabsf(fmaf(((const float*)&a)[j], 1.0f/255.0f,
                                     -((const float*)&p)[j])), EPS);
            dc[j] = 0.0f;
        }
        #pragma unroll
        for (int ch = 0; ch < 3; ch++) {         // channel-incremental
            const float4 im = __ldcs(im4 + i + ch * CH4);
            const float4 ff = __ldcs(fg4 + i + ch * CH4);
            const float4 gg = __ldcs(bg4 + i + ch * CH4);
            #pragma unroll
            for (int j = 0; j < 4; j++) {
                float pj = ((const float*)&p)[j];
                float tt = fmaf(((const float*)&ff)[j] - ((const float*)&gg)[j], pj,
                                ((const float*)&gg)[j]);
                dc[j] += fmaxf(fabsf(((const float*)&im)[j] - tt), EPS);
            }
        }
        #pragma unroll
        for (int j = 0; j < 4; j++) {
            if (((const int*)&t)[j] == 128) {
                unsigned ca = (unsigned)__half_as_ushort(__float2half_rn(da[j]));
                unsigned cc = (unsigned)__half_as_ushort(__float2half_rn(dc[j]));
                ca = min(ca, (unsigned)(NB - 1));          // provable no-op; memory safety
                cc = min(cc, (unsigned)(NB - 1));
                atomicAdd(&sh[ca >> 1],        1u << ((ca & 1u) << 4));
                atomicAdd(&sh[NW + (cc >> 1)], 1u << ((cc & 1u) << 4));
                cnt++;
            }
        }
    }
    cnt = __reduce_add_sync(0xFFFFFFFFu, cnt);
    if ((threadIdx.x & 31) == 0 && cnt) atomicAdd(&shCnt, cnt);
    __syncthreads();
    if (threadIdx.x == 0 && shCnt) atomicAdd(&g_count[b], shCnt);

    // flush nonzero packed words to the global exact histogram
    for (int i = threadIdx.x; i < 2 * NW; i += TPB1) {
        unsigned wv = sh[i];
        if (wv) {
            const int arr = (i >= NW);
            const int wi  = arr ? (i - NW) : i;
            unsigned* gh = g_hist[arr][b];
            unsigned lo = wv & 0xFFFFu, hi = wv >> 16;
            if (lo) atomicAdd(&gh[2 * wi],     lo);
            if (hi) atomicAdd(&gh[2 * wi + 1], hi);
        }
    }
}

// ---------------- K2: exact descending scan + integer top-k sum + finish ----
__global__ __launch_bounds__(TPB2) void k_select(float* __restrict__ out) {
    __shared__ unsigned s_wsum[17];
    __shared__ unsigned s_cut, s_krem;
    __shared__ unsigned long long s_sum;
    __shared__ bool s_last;

    const int arr = blockIdx.x >> 3;
    const int b   = blockIdx.x & 7;
    const int t   = threadIdx.x;
    const int lane = t & 31, w = t >> 5;
    unsigned* hist = g_hist[arr][b];

    if (t == 0) { s_cut = 0xFFFFFFFFu; s_krem = 0u; s_sum = 0ull; }

    // thread t owns codes [lo, lo+31], lo = NB-32(t+1); t ascending = value descending
    const int lo = NB - 32 * (t + 1);
    unsigned cnts[32];
    {
        uint4* hp = (uint4*)&hist[lo];
        #pragma unroll
        for (int q = 0; q < 8; q++) {
            uint4 v = hp[q];
            cnts[4*q] = v.x; cnts[4*q+1] = v.y; cnts[4*q+2] = v.z; cnts[4*q+3] = v.w;
            hp[q] = make_uint4(0u, 0u, 0u, 0u);            // self-clean for next replay
        }
    }
    unsigned seg = 0;
    #pragma unroll
    for (int j = 0; j < 32; j++) seg += cnts[j];

    // block-wide inclusive scan over seg (t ascending = descending value order)
    unsigned incl = seg;
    #pragma unroll
    for (int d = 1; d < 32; d <<= 1) {
        unsigned v = __shfl_up_sync(0xFFFFFFFFu, incl, d);
        if (lane >= d) incl += v;
    }
    if (lane == 31) s_wsum[w] = incl;
    __syncthreads();
    if (t == 0) {
        unsigned run = 0;
        #pragma unroll
        for (int i = 0; i < 17; i++) { unsigned v = s_wsum[i]; s_wsum[i] = run; run += v; }
    }
    __syncthreads();
    incl += s_wsum[w];

    const unsigned k = (unsigned)(int)floorf((float)g_count[b] * 0.7f);
    {
        unsigned excl = incl - seg;
        if (k > 0u && excl < k && incl >= k) {             // exactly one owner thread
            unsigned cum = excl;
            #pragma unroll
            for (int j = 31; j >= 0; j--) {                // descending code order
                cum += cnts[j];
                if (cum >= k) {
                    s_cut  = (unsigned)(lo + j);
                    s_krem = k - (cum - cnts[j]);          // >= 1
                    break;
                }
            }
        }
    }
    __syncthreads();
    const unsigned cut = s_cut;

    // pure-integer fixed-point sum of count*value for codes above cut
    unsigned long long part = 0ull;
    #pragma unroll
    for (int j = 0; j < 32; j++) {
        unsigned code = (unsigned)(lo + j);
        if (code > cut && cnts[j])
            part += (unsigned long long)cnts[j] * h2fx(code);
    }
    if (t == 0 && cut != 0xFFFFFFFFu)                      // tie-exact cut-bin take
        part += (unsigned long long)s_krem * h2fx(cut);
    if (part) atomicAdd(&s_sum, part);
    __syncthreads();
    if (t == 0) {
        g_loss[arr][b] = s_sum;
        __threadfence();
        s_last = (atomicAdd(&g_done, 1u) == 15u);
    }
    __syncthreads();
    if (!s_last) return;

    if (t == 0) {                                          // final combine (16 values)
        __threadfence();
        double sA = 0.0, sC = 0.0;
        for (int i = 0; i < BATCH; i++) {
            float kf = floorf((float)g_count[i] * 0.7f);
            if (kf > 0.0f) {
                sA += ((double)g_loss[0][i] / SCALE_D) / ((double)kf + 1e-6);
                sC += ((double)g_loss[1][i] / SCALE_D) / ((double)kf + 1e-6);
            }
        }
        out[0] = 0.5f * (float)(sA / (double)BATCH) + 0.5f * (float)(sC / (double)BATCH);
        g_done = 0u;
        for (int i = 0; i < BATCH; i++) g_count[i] = 0u;   // self-clean
    }
}

// ---------------- launch ----------------
extern "C" void kernel_launch(void* const* d_in, const int* in_sizes, int n_in,
                              void* d_out, int out_size)
{
    const float* image  = (const float*)d_in[0];
    const float* alpha  = (const float*)d_in[1];
    const float* pred   = (const float*)d_in[2];
    const int*   trimap = (const int*)  d_in[3];
    const float* fg     = (const float*)d_in[4];
    const float* bg     = (const float*)d_in[5];

    static bool attr_set = false;
    if (!attr_set) {
        cudaFuncSetAttribute(k_compute, cudaFuncAttributeMaxDynamicSharedMemorySize,
                             2 * NW * (int)sizeof(unsigned));
        attr_set = true;
    }

    k_compute<<<BATCH * BPS, TPB1, 2 * NW * sizeof(unsigned)>>>(
        image, alpha, pred, trimap, fg, bg);
    k_select<<<16, TPB2>>>((float*)d_out);
}

// round 15
// speedup vs baseline: 1.9856x; 1.1232x over previous
#include <cuda_runtime.h>
#include <cuda_fp16.h>

#define BATCH 8
#define NPX   (512*512)          // 262144 pixels per sample
#define BPS   32                 // K1 blocks per sample -> 256 blocks
#define TPB1  512
#define NB    17408              // full fp16-code histogram (max code 0x4200=16896 < NB)
#define NW    (NB/2)             // packed u32 words per smem histogram
#define NCH   544                // coarse chunks (32 codes each)
#define PARTS 16                 // K2 blocks per (arr,sample)
#define PWORDS (NB/PARTS)        // 1088 codes per K2 block = 34 chunks
#define TPB2  544
#define EPS   1e-6f
#define SCALE_D 1099511627776.0  // 2^40 (final normalize only)

// ---------------- device scratch (zero-init at load; self-cleaning each run) ----
__device__ unsigned  g_hist[2][BATCH][NB];       // exact per-code counts (u32)
__device__ unsigned  g_coarse[2][BATCH][NCH];    // per-32-code-chunk sums
__device__ unsigned  g_count[BATCH];             // # unknown pixels per sample
__device__ unsigned long long g_loss[2][BATCH];  // fixed-point top-k sums
__device__ unsigned  g_done;                     // K2 completion counter

// exact u64 fixed-point (x 2^40) decode of a half bit pattern (positive, < 2^15)
__device__ __forceinline__ unsigned long long h2fx(unsigned code) {
    unsigned e = code >> 10, m = code & 1023u;
    return e ? ((unsigned long long)(1024u + m) << (e + 15))
             : ((unsigned long long)m << 16);
}

// ---------------- K1: fused value compute + count + exact & coarse histograms ----
__global__ __launch_bounds__(TPB1) void k_compute(
    const float* __restrict__ image, const float* __restrict__ alpha,
    const float* __restrict__ pred,  const int*   __restrict__ trimap,
    const float* __restrict__ fg,    const float* __restrict__ bg)
{
    extern __shared__ unsigned sh[];             // [0..NW): A hist, [NW..2NW): C hist
    __shared__ unsigned shCnt;
    for (int i = threadIdx.x; i < 2 * NW; i += TPB1) sh[i] = 0u;
    if (threadIdx.x == 0) shCnt = 0u;
    __syncthreads();

    const int b     = blockIdx.x >> 5;           // / BPS
    const int chunk = blockIdx.x & (BPS - 1);
    const int base  = chunk * (NPX / BPS);       // 8192-pixel chunk
    const int CH4   = NPX / 4;                   // channel stride in float4

    const float4* al4 = (const float4*)(alpha  + (size_t)b * NPX + base);
    const float4* pr4 = (const float4*)(pred   + (size_t)b * NPX + base);
    const int4*   tm4 = (const int4*)  (trimap + (size_t)b * NPX + base);
    const float4* im4 = (const float4*)(image  + (size_t)b * 3 * NPX + base);
    const float4* fg4 = (const float4*)(fg     + (size_t)b * 3 * NPX + base);
    const float4* bg4 = (const float4*)(bg     + (size_t)b * 3 * NPX + base);

    unsigned cnt = 0;
    #pragma unroll
    for (int it = 0; it < (NPX / BPS) / 4 / TPB1; it++) {   // 4 iterations
        const int i = it * TPB1 + threadIdx.x;
        const int4   t = __ldcs(tm4 + i);
        const float4 a = __ldcs(al4 + i);
        const float4 p = __ldcs(pr4 + i);

        float da[4], dc[4];
        #pragma unroll
        for (int j = 0; j < 4; j++) {
            da[j] = fmaxf(fabsf(fmaf(((const float*)&a)[j], 1.0f/255.0f,
                                     -((const float*)&p)[j])), EPS);
            dc[j] = 0.0f;
        }
        #pragma unroll
        for (int ch = 0; ch < 3; ch++) {         // channel-incremental
            const float4 im = __ldcs(im4 + i + ch * CH4);
            const float4 ff = __ldcs(fg4 + i + ch * CH4);
            const float4 gg = __ldcs(bg4 + i + ch * CH4);
            #pragma unroll
            for (int j = 0; j < 4; j++) {
                float pj = ((const float*)&p)[j];
                float tt = fmaf(((const float*)&ff)[j] - ((const float*)&gg)[j], pj,
                                ((const float*)&gg)[j]);
                dc[j] += fmaxf(fabsf(((const float*)&im)[j] - tt), EPS);
            }
        }
        #pragma unroll
        for (int j = 0; j < 4; j++) {
            if (((const int*)&t)[j] == 128) {
                unsigned ca = (unsigned)__half_as_ushort(__float2half_rn(da[j]));
                unsigned cc = (unsigned)__half_as_ushort(__float2half_rn(dc[j]));
                ca = min(ca, (unsigned)(NB - 1));          // provable no-op; memory safety
                cc = min(cc, (unsigned)(NB - 1));
                atomicAdd(&sh[ca >> 1],        1u << ((ca & 1u) << 4));
                atomicAdd(&sh[NW + (cc >> 1)], 1u << ((cc & 1u) << 4));
                cnt++;
            }
        }
    }
    cnt = __reduce_add_sync(0xFFFFFFFFu, cnt);
    if ((threadIdx.x & 31) == 0 && cnt) atomicAdd(&shCnt, cnt);
    __syncthreads();
    if (threadIdx.x == 0 && shCnt) atomicAdd(&g_count[b], shCnt);

    // flush nonzero packed words to the global exact histogram
    for (int i = threadIdx.x; i < 2 * NW; i += TPB1) {
        unsigned wv = sh[i];
        if (wv) {
            const int arr = (i >= NW);
            const int wi  = arr ? (i - NW) : i;
            unsigned* gh = g_hist[arr][b];
            unsigned lo = wv & 0xFFFFu, hi = wv >> 16;
            if (lo) atomicAdd(&gh[2 * wi],     lo);
            if (hi) atomicAdd(&gh[2 * wi + 1], hi);
        }
    }
    // flush coarse per-chunk sums (32 codes = 16 packed words per chunk)
    for (int c = threadIdx.x; c < 2 * NCH; c += TPB1) {
        const int arr = (c >= NCH);
        const int ci  = arr ? c - NCH : c;
        const unsigned* bw = &sh[arr * NW + ci * 16];
        unsigned s = 0;
        #pragma unroll
        for (int q = 0; q < 16; q++) { unsigned w = bw[q]; s += (w & 0xFFFFu) + (w >> 16); }
        if (s) atomicAdd(&g_coarse[arr][b][ci], s);
    }
}

// ---------------- K2: coarse cut-scan + parallel exact top-k sum + finish ----
__global__ __launch_bounds__(TPB2) void k_select(float* __restrict__ out) {
    __shared__ unsigned s_wsum[17];
    __shared__ int      s_C;                     // cut chunk (-1 = none)
    __shared__ unsigned s_rem;                   // count to take from cut chunk
    __shared__ unsigned s_chunk[32];             // cut chunk's exact counts
    __shared__ unsigned long long s_sum;
    __shared__ bool s_last;

    const int p   = blockIdx.x & (PARTS - 1);
    const int b   = (blockIdx.x >> 4) & 7;
    const int arr = blockIdx.x >> 7;
    const int t   = threadIdx.x;
    const int lane = t & 31, w = t >> 5;

    if (t == 0) { s_C = -1; s_rem = 0u; s_sum = 0ull; }

    // ---- descending scan of coarse hist: thread t owns chunk (NCH-1-t) ----
    const unsigned seg = g_coarse[arr][b][NCH - 1 - t];
    unsigned incl = seg;
    #pragma unroll
    for (int d = 1; d < 32; d <<= 1) {
        unsigned v = __shfl_up_sync(0xFFFFFFFFu, incl, d);
        if (lane >= d) incl += v;
    }
    if (lane == 31) s_wsum[w] = incl;
    __syncthreads();
    if (t == 0) {
        unsigned run = 0;
        #pragma unroll
        for (int i = 0; i < 17; i++) { unsigned v = s_wsum[i]; s_wsum[i] = run; run += v; }
    }
    __syncthreads();
    incl += s_wsum[w];

    const unsigned k = (unsigned)(int)floorf((float)g_count[b] * 0.7f);
    {
        unsigned excl = incl - seg;
        if (k > 0u && excl < k && incl >= k) {   // exactly one owner thread
            s_C   = NCH - 1 - t;
            s_rem = k - excl;                    // take this many from chunk C (>=1)
        }
    }
    __syncthreads();
    const int C = s_C;

    // ---- this block's 1088-code slice of the exact histogram ----
    unsigned* hist = g_hist[arr][b];
    const int w0 = p * PWORDS + 2 * t;           // two consecutive codes per thread
    uint2 cv = *(uint2*)&hist[w0];
    *(uint2*)&hist[w0] = make_uint2(0u, 0u);     // self-clean for next replay

    unsigned long long part = 0ull;
    const int cc = w0 >> 5;                      // chunk of both codes (w0 even)
    if (C >= 0 && cc > C) {
        if (cv.x) part += (unsigned long long)cv.x * h2fx((unsigned)w0);
        if (cv.y) part += (unsigned long long)cv.y * h2fx((unsigned)(w0 + 1));
    } else if (cc == C) {                        // deposit cut chunk's exact counts
        s_chunk[w0 & 31]       = cv.x;
        s_chunk[(w0 + 1) & 31] = cv.y;
    }
    __syncthreads();
    // owner block (chunk C in [34p, 34p+34)) resolves exact descending take
    if (t == 0 && C >= 0 && (C / 34) == p) {
        unsigned rem = s_rem;
        for (int j = 31; j >= 0 && rem > 0u; j--) {
            unsigned cj = s_chunk[j];
            if (!cj) continue;
            unsigned take = cj < rem ? cj : rem;
            part += (unsigned long long)take * h2fx((unsigned)(C * 32 + j));
            rem -= take;
        }
    }
    // warp reduce (u64) then per-warp shared atomic, then one global atomic
    #pragma unroll
    for (int o = 16; o; o >>= 1) part += __shfl_xor_sync(0xFFFFFFFFu, part, o);
    if (lane == 0 && part) atomicAdd(&s_sum, part);
    __syncthreads();
    if (t == 0 && s_sum) atomicAdd(&g_loss[arr][b], s_sum);

    // ---- last-block finish ----
    __threadfence();
    __syncthreads();
    if (t == 0) s_last = (atomicAdd(&g_done, 1u) == (unsigned)(gridDim.x - 1));
    __syncthreads();
    if (!s_last) return;
    __threadfence();

    // zero coarse hist for next replay (2*8*544 words)
    for (int i = t; i < 2 * BATCH * NCH; i += TPB2) ((unsigned*)g_coarse)[i] = 0u;
    if (t == 0) {
        double sA = 0.0, sC2 = 0.0;
        for (int i = 0; i < BATCH; i++) {
            float kf = floorf((float)g_count[i] * 0.7f);
            if (kf > 0.0f) {
                sA  += ((double)g_loss[0][i] / SCALE_D) / ((double)kf + 1e-6);
                sC2 += ((double)g_loss[1][i] / SCALE_D) / ((double)kf + 1e-6);
            }
        }
        out[0] = 0.5f * (float)(sA / (double)BATCH) + 0.5f * (float)(sC2 / (double)BATCH);
        for (int i = 0; i < BATCH; i++) {
            g_count[i] = 0u;
            g_loss[0][i] = 0ull; g_loss[1][i] = 0ull;
        }
        g_done = 0u;
    }
}

// ---------------- launch ----------------
extern "C" void kernel_launch(void* const* d_in, const int* in_sizes, int n_in,
                              void* d_out, int out_size)
{
    const float* image  = (const float*)d_in[0];
    const float* alpha  = (const float*)d_in[1];
    const float* pred   = (const float*)d_in[2];
    const int*   trimap = (const int*)  d_in[3];
    const float* fg     = (const float*)d_in[4];
    const float* bg     = (const float*)d_in[5];

    static bool attr_set = false;
    if (!attr_set) {
        cudaFuncSetAttribute(k_compute, cudaFuncAttributeMaxDynamicSharedMemorySize,
                             2 * NW * (int)sizeof(unsigned));
        attr_set = true;
    }

    k_compute<<<BATCH * BPS, TPB1, 2 * NW * sizeof(unsigned)>>>(
        image, alpha, pred, trimap, fg, bg);
    k_select<<<2 * BATCH * PARTS, TPB2>>>((float*)d_out);
}

// round 17
// speedup vs baseline: 2.1159x; 1.0656x over previous
#include <cuda_runtime.h>
#include <cuda_fp16.h>

#define BATCH 8
#define NPX   (512*512)          // 262144 pixels per sample
#define BPS   32                 // K1 blocks per sample -> 256 blocks
#define TPB1  512
#define NB    17408              // full fp16-code histogram (max code 0x4200=16896 < NB)
#define NW    (NB/2)             // packed u32 words per smem histogram
#define NCH   544                // coarse chunks (32 codes each)
#define PARTS 16                 // K2 blocks per (arr,sample)
#define PWORDS (NB/PARTS)        // 1088 codes per K2 block = 34 chunks
#define TPB2  544
#define EPS   1e-6f
#define SCALE_D 1099511627776.0  // 2^40 (final normalize only)

// ---------------- device scratch (zero-init at load; self-cleaning each run) ----
__device__ unsigned  g_hist[2][BATCH][NB];       // exact per-code counts (u32)
__device__ unsigned  g_coarse[2][BATCH][NCH];    // per-32-code-chunk sums
__device__ unsigned  g_count[BATCH];             // # unknown pixels per sample
__device__ unsigned long long g_loss[2][BATCH];  // fixed-point top-k sums

// exact u64 fixed-point (x 2^40) decode of a half bit pattern (positive, < 2^15)
__device__ __forceinline__ unsigned long long h2fx(unsigned code) {
    unsigned e = code >> 10, m = code & 1023u;
    return e ? ((unsigned long long)(1024u + m) << (e + 15))
             : ((unsigned long long)m << 16);
}

// ---------------- K1: fused value compute + count + exact & coarse histograms ----
__global__ __launch_bounds__(TPB1) void k_compute(
    const float* __restrict__ image, const float* __restrict__ alpha,
    const float* __restrict__ pred,  const int*   __restrict__ trimap,
    const float* __restrict__ fg,    const float* __restrict__ bg)
{
    extern __shared__ unsigned sh[];             // [0..NW): A hist, [NW..2NW): C hist
    __shared__ unsigned shCnt;
    for (int i = threadIdx.x; i < 2 * NW; i += TPB1) sh[i] = 0u;
    if (threadIdx.x == 0) shCnt = 0u;
    __syncthreads();

    const int b     = blockIdx.x >> 5;           // / BPS
    const int chunk = blockIdx.x & (BPS - 1);
    const int base  = chunk * (NPX / BPS);       // 8192-pixel chunk
    const int CH4   = NPX / 4;                   // channel stride in float4

    const float4* al4 = (const float4*)(alpha  + (size_t)b * NPX + base);
    const float4* pr4 = (const float4*)(pred   + (size_t)b * NPX + base);
    const int4*   tm4 = (const int4*)  (trimap + (size_t)b * NPX + base);
    const float4* im4 = (const float4*)(image  + (size_t)b * 3 * NPX + base);
    const float4* fg4 = (const float4*)(fg     + (size_t)b * 3 * NPX + base);
    const float4* bg4 = (const float4*)(bg     + (size_t)b * 3 * NPX + base);

    unsigned cnt = 0;
    #pragma unroll
    for (int it = 0; it < (NPX / BPS) / 4 / TPB1; it++) {   // 4 iterations
        const int i = it * TPB1 + threadIdx.x;
        const int4   t = __ldcs(tm4 + i);
        const float4 a = __ldcs(al4 + i);
        const float4 p = __ldcs(pr4 + i);

        float da[4], dc[4];
        #pragma unroll
        for (int j = 0; j < 4; j++) {
            da[j] = fmaxf(fabsf(fmaf(((const float*)&a)[j], 1.0f/255.0f,
                                     -((const float*)&p)[j])), EPS);
            dc[j] = 0.0f;
        }
        #pragma unroll
        for (int ch = 0; ch < 3; ch++) {         // channel-incremental
            const float4 im = __ldcs(im4 + i + ch * CH4);
            const float4 ff = __ldcs(fg4 + i + ch * CH4);
            const float4 gg = __ldcs(bg4 + i + ch * CH4);
            #pragma unroll
            for (int j = 0; j < 4; j++) {
                float pj = ((const float*)&p)[j];
                float tt = fmaf(((const float*)&ff)[j] - ((const float*)&gg)[j], pj,
                                ((const float*)&gg)[j]);
                dc[j] += fmaxf(fabsf(((const float*)&im)[j] - tt), EPS);
            }
        }
        #pragma unroll
        for (int j = 0; j < 4; j++) {
            if (((const int*)&t)[j] == 128) {
                unsigned ca = (unsigned)__half_as_ushort(__float2half_rn(da[j]));
                unsigned cc = (unsigned)__half_as_ushort(__float2half_rn(dc[j]));
                ca = min(ca, (unsigned)(NB - 1));          // provable no-op; memory safety
                cc = min(cc, (unsigned)(NB - 1));
                atomicAdd(&sh[ca >> 1],        1u << ((ca & 1u) << 4));
                atomicAdd(&sh[NW + (cc >> 1)], 1u << ((cc & 1u) << 4));
                cnt++;
            }
        }
    }
    cnt = __reduce_add_sync(0xFFFFFFFFu, cnt);
    if ((threadIdx.x & 31) == 0 && cnt) atomicAdd(&shCnt, cnt);
    __syncthreads();
    if (threadIdx.x == 0 && shCnt) atomicAdd(&g_count[b], shCnt);

    // flush nonzero packed words to the global exact histogram
    for (int i = threadIdx.x; i < 2 * NW; i += TPB1) {
        unsigned wv = sh[i];
        if (wv) {
            const int arr = (i >= NW);
            const int wi  = arr ? (i - NW) : i;
            unsigned* gh = g_hist[arr][b];
            unsigned lo = wv & 0xFFFFu, hi = wv >> 16;
            if (lo) atomicAdd(&gh[2 * wi],     lo);
            if (hi) atomicAdd(&gh[2 * wi + 1], hi);
        }
    }
    // flush coarse per-chunk sums (32 codes = 16 packed words per chunk)
    for (int c = threadIdx.x; c < 2 * NCH; c += TPB1) {
        const int arr = (c >= NCH);
        const int ci  = arr ? c - NCH : c;
        const unsigned* bw = &sh[arr * NW + ci * 16];
        unsigned s = 0;
        #pragma unroll
        for (int q = 0; q < 16; q++) { unsigned w = bw[q]; s += (w & 0xFFFFu) + (w >> 16); }
        if (s) atomicAdd(&g_coarse[arr][b][ci], s);
    }
}

// ---------------- K2: coarse cut-scan + parallel exact top-k sum (no fences) ----
__global__ __launch_bounds__(TPB2) void k_select() {
    __shared__ unsigned s_wsum[17];
    __shared__ int      s_C;                     // cut chunk (-1 = none)
    __shared__ unsigned s_rem;                   // count to take from cut chunk
    __shared__ unsigned s_chunk[32];             // cut chunk's exact counts
    __shared__ unsigned long long s_sum;

    const int p   = blockIdx.x & (PARTS - 1);
    const int b   = (blockIdx.x >> 4) & 7;
    const int arr = blockIdx.x >> 7;
    const int t   = threadIdx.x;
    const int lane = t & 31, w = t >> 5;

    if (t == 0) { s_C = -1; s_rem = 0u; s_sum = 0ull; }

    // ---- descending scan of coarse hist: thread t owns chunk (NCH-1-t) ----
    const unsigned seg = g_coarse[arr][b][NCH - 1 - t];
    unsigned incl = seg;
    #pragma unroll
    for (int d = 1; d < 32; d <<= 1) {
        unsigned v = __shfl_up_sync(0xFFFFFFFFu, incl, d);
        if (lane >= d) incl += v;
    }
    if (lane == 31) s_wsum[w] = incl;
    __syncthreads();
    if (t == 0) {
        unsigned run = 0;
        #pragma unroll
        for (int i = 0; i < 17; i++) { unsigned v = s_wsum[i]; s_wsum[i] = run; run += v; }
    }
    __syncthreads();
    incl += s_wsum[w];

    const unsigned k = (unsigned)(int)floorf((float)g_count[b] * 0.7f);
    {
        unsigned excl = incl - seg;
        if (k > 0u && excl < k && incl >= k) {   // exactly one owner thread
            s_C   = NCH - 1 - t;
            s_rem = k - excl;                    // take this many from chunk C (>=1)
        }
    }
    __syncthreads();
    const int C = s_C;

    // ---- this block's 1088-code slice of the exact histogram ----
    unsigned* hist = g_hist[arr][b];
    const int w0 = p * PWORDS + 2 * t;           // two consecutive codes per thread
    uint2 cv = *(uint2*)&hist[w0];
    *(uint2*)&hist[w0] = make_uint2(0u, 0u);     // self-clean for next replay

    unsigned long long part = 0ull;
    const int cc = w0 >> 5;                      // chunk of both codes (w0 even)
    if (C >= 0 && cc > C) {
        if (cv.x) part += (unsigned long long)cv.x * h2fx((unsigned)w0);
        if (cv.y) part += (unsigned long long)cv.y * h2fx((unsigned)(w0 + 1));
    } else if (cc == C) {                        // deposit cut chunk's exact counts
        s_chunk[w0 & 31]       = cv.x;
        s_chunk[(w0 + 1) & 31] = cv.y;
    }
    __syncthreads();
    // owner block (chunk C in [34p, 34p+34)) resolves exact descending take
    if (t == 0 && C >= 0 && (C / 34) == p) {
        unsigned rem = s_rem;
        for (int j = 31; j >= 0 && rem > 0u; j--) {
            unsigned cj = s_chunk[j];
            if (!cj) continue;
            unsigned take = cj < rem ? cj : rem;
            part += (unsigned long long)take * h2fx((unsigned)(C * 32 + j));
            rem -= take;
        }
    }
    // warp reduce (u64), one shared atomic per warp, one global atomic per block
    #pragma unroll
    for (int o = 16; o; o >>= 1) part += __shfl_xor_sync(0xFFFFFFFFu, part, o);
    if (lane == 0 && part) atomicAdd(&s_sum, part);
    __syncthreads();
    if (t == 0 && s_sum) atomicAdd(&g_loss[arr][b], s_sum);
}

// ---------------- K3: tiny finish + cleanup (kernel boundary = ordering) ----
__global__ __launch_bounds__(512) void k_final(float* __restrict__ out) {
    const int t = threadIdx.x;
    if (blockIdx.x != 0) {
        // blocks 1..17 zero the coarse hist: 17 * 512 = 8704 words exactly
        ((unsigned*)g_coarse)[(blockIdx.x - 1) * 512 + t] = 0u;
        return;
    }
    if (t == 0) {
        double sA = 0.0, sC = 0.0;
        for (int i = 0; i < BATCH; i++) {
            float kf = floorf((float)g_count[i] * 0.7f);
            if (kf > 0.0f) {
                sA += ((double)g_loss[0][i] / SCALE_D) / ((double)kf + 1e-6);
                sC += ((double)g_loss[1][i] / SCALE_D) / ((double)kf + 1e-6);
            }
        }
        out[0] = 0.5f * (float)(sA / (double)BATCH) + 0.5f * (float)(sC / (double)BATCH);
    }
    if (t < BATCH)     g_count[t] = 0u;                       // self-clean
    if (t < 2 * BATCH) ((unsigned long long*)g_loss)[t] = 0ull;
}

// ---------------- launch ----------------
extern "C" void kernel_launch(void* const* d_in, const int* in_sizes, int n_in,
                              void* d_out, int out_size)
{
    const float* image  = (const float*)d_in[0];
    const float* alpha  = (const float*)d_in[1];
    const float* pred   = (const float*)d_in[2];
    const int*   trimap = (const int*)  d_in[3];
    const float* fg     = (const float*)d_in[4];
    const float* bg     = (const float*)d_in[5];

    static bool attr_set = false;
    if (!attr_set) {
        cudaFuncSetAttribute(k_compute, cudaFuncAttributeMaxDynamicSharedMemorySize,
                             2 * NW * (int)sizeof(unsigned));
        attr_set = true;
    }

    k_compute<<<BATCH * BPS, TPB1, 2 * NW * sizeof(unsigned)>>>(
        image, alpha, pred, trimap, fg, bg);
    k_select<<<2 * BATCH * PARTS, TPB2>>>();
    k_final<<<18, 512>>>((float*)d_out);
}